// round 2
// baseline (speedup 1.0000x reference)
#include <cuda_runtime.h>
#include <math.h>

#define BB   2
#define SS   4096
#define DIM  1024
#define AD   1024
#define QKV3 (3*AD)

// Scratch (device globals; no dynamic allocation allowed)
__device__ float g_qkv[(size_t)BB*SS*QKV3];   // [B, S, 3*AD]  ~100 MB
__device__ float g_sc [(size_t)BB*SS*SS];     // [B, S, S]     ~134 MB

// ---------------------------------------------------------------------------
// Kernel 1: QKV = x @ W^T + b      (M=B*S=8192, N=3072, K=1024, both K-major)
// 128x128 tile, BK=16, 256 threads, 8x8 per-thread micro-tile
// ---------------------------------------------------------------------------
__global__ __launch_bounds__(256) void qkv_kernel(const float* __restrict__ x,
                                                  const float* __restrict__ W,
                                                  const float* __restrict__ bias)
{
    __shared__ float As[16][128];
    __shared__ float Bs[16][128];
    const int tid = threadIdx.x;
    const int tx = tid & 15, ty = tid >> 4;
    const int m0 = blockIdx.y * 128, n0 = blockIdx.x * 128;
    const float* A = x + (size_t)m0 * DIM;
    const float* Bp = W + (size_t)n0 * DIM;

    float acc[8][8] = {};

    for (int k0 = 0; k0 < DIM; k0 += 16) {
        #pragma unroll
        for (int q = 0; q < 2; ++q) {
            int f  = tid * 2 + q;        // 0..511
            int m  = f >> 2;
            int kq = (f & 3) * 4;
            float4 va = *(const float4*)&A [(size_t)m * DIM + k0 + kq];
            As[kq+0][m] = va.x; As[kq+1][m] = va.y; As[kq+2][m] = va.z; As[kq+3][m] = va.w;
            float4 vb = *(const float4*)&Bp[(size_t)m * DIM + k0 + kq];
            Bs[kq+0][m] = vb.x; Bs[kq+1][m] = vb.y; Bs[kq+2][m] = vb.z; Bs[kq+3][m] = vb.w;
        }
        __syncthreads();
        #pragma unroll
        for (int k = 0; k < 16; ++k) {
            float4 a0 = *(const float4*)&As[k][ty*8];
            float4 a1 = *(const float4*)&As[k][ty*8+4];
            float4 b0 = *(const float4*)&Bs[k][tx*8];
            float4 b1 = *(const float4*)&Bs[k][tx*8+4];
            float a[8] = {a0.x,a0.y,a0.z,a0.w,a1.x,a1.y,a1.z,a1.w};
            float b[8] = {b0.x,b0.y,b0.z,b0.w,b1.x,b1.y,b1.z,b1.w};
            #pragma unroll
            for (int i = 0; i < 8; ++i)
                #pragma unroll
                for (int j = 0; j < 8; ++j)
                    acc[i][j] += a[i] * b[j];
        }
        __syncthreads();
    }

    #pragma unroll
    for (int i = 0; i < 8; ++i) {
        size_t row = (size_t)(m0 + ty*8 + i);
        #pragma unroll
        for (int j = 0; j < 8; ++j) {
            int col = n0 + tx*8 + j;
            g_qkv[row * QKV3 + col] = acc[i][j] + bias[col];
        }
    }
}

// ---------------------------------------------------------------------------
// Kernel 2: scores = Q @ K^T  (per batch, lower-triangular blocks only)
// ---------------------------------------------------------------------------
__global__ __launch_bounds__(256) void scores_kernel()
{
    const int bx = blockIdx.x, by = blockIdx.y, b = blockIdx.z;
    if (bx > by) return;                       // strictly-upper block: never read

    __shared__ float As[16][128];
    __shared__ float Bs[16][128];
    const int tid = threadIdx.x;
    const int tx = tid & 15, ty = tid >> 4;
    const int m0 = by * 128, n0 = bx * 128;
    const float* Q = g_qkv + (size_t)b * SS * QKV3 + (size_t)m0 * QKV3;        // q rows
    const float* K = g_qkv + (size_t)b * SS * QKV3 + (size_t)n0 * QKV3 + AD;   // k rows

    float acc[8][8] = {};

    for (int k0 = 0; k0 < AD; k0 += 16) {
        #pragma unroll
        for (int q = 0; q < 2; ++q) {
            int f  = tid * 2 + q;
            int m  = f >> 2;
            int kq = (f & 3) * 4;
            float4 va = *(const float4*)&Q[(size_t)m * QKV3 + k0 + kq];
            As[kq+0][m] = va.x; As[kq+1][m] = va.y; As[kq+2][m] = va.z; As[kq+3][m] = va.w;
            float4 vb = *(const float4*)&K[(size_t)m * QKV3 + k0 + kq];
            Bs[kq+0][m] = vb.x; Bs[kq+1][m] = vb.y; Bs[kq+2][m] = vb.z; Bs[kq+3][m] = vb.w;
        }
        __syncthreads();
        #pragma unroll
        for (int k = 0; k < 16; ++k) {
            float4 a0 = *(const float4*)&As[k][ty*8];
            float4 a1 = *(const float4*)&As[k][ty*8+4];
            float4 b0 = *(const float4*)&Bs[k][tx*8];
            float4 b1 = *(const float4*)&Bs[k][tx*8+4];
            float a[8] = {a0.x,a0.y,a0.z,a0.w,a1.x,a1.y,a1.z,a1.w};
            float bb[8] = {b0.x,b0.y,b0.z,b0.w,b1.x,b1.y,b1.z,b1.w};
            #pragma unroll
            for (int i = 0; i < 8; ++i)
                #pragma unroll
                for (int j = 0; j < 8; ++j)
                    acc[i][j] += a[i] * bb[j];
        }
        __syncthreads();
    }

    float* outb = g_sc + (size_t)b * SS * SS;
    #pragma unroll
    for (int i = 0; i < 8; ++i) {
        size_t row = (size_t)(m0 + ty*8 + i);
        #pragma unroll
        for (int j = 0; j < 8; ++j)
            outb[row * SS + (n0 + tx*8 + j)] = acc[i][j];
    }
}

// ---------------------------------------------------------------------------
// Kernel 3: causal row softmax, score scaled by 1/sqrt(AD)=1/32.
// Writes normalized probs for j<=i, zeros for j>i (so PV needs no masking).
// ---------------------------------------------------------------------------
__global__ __launch_bounds__(256) void softmax_kernel()
{
    const int i = blockIdx.x;
    const int b = blockIdx.y;
    const int tid = threadIdx.x;
    float* row = g_sc + (size_t)b * SS * SS + (size_t)i * SS;
    const int len = i + 1;
    const float inv = 1.0f / 32.0f;

    __shared__ float red[256];

    // pass 1: max
    float m = -3.4e38f;
    for (int j = tid; j < len; j += 256) m = fmaxf(m, row[j]);
    red[tid] = m; __syncthreads();
    for (int s = 128; s > 0; s >>= 1) {
        if (tid < s) red[tid] = fmaxf(red[tid], red[tid + s]);
        __syncthreads();
    }
    m = red[0]; __syncthreads();

    // pass 2: exp + sum (overwrite in place)
    float sum = 0.0f;
    for (int j = tid; j < len; j += 256) {
        float e = expf((row[j] - m) * inv);
        row[j] = e;
        sum += e;
    }
    red[tid] = sum; __syncthreads();
    for (int s = 128; s > 0; s >>= 1) {
        if (tid < s) red[tid] += red[tid + s];
        __syncthreads();
    }
    const float r = 1.0f / red[0];

    // pass 3: normalize + zero the causal tail
    for (int j = tid; j < len; j += 256) row[j] *= r;
    for (int j = len + tid; j < SS; j += 256) row[j] = 0.0f;
}

// ---------------------------------------------------------------------------
// Kernel 4: y = P @ V   (M=S, N=AD, K truncated at causal boundary)
// P row-major [S,S] (K contiguous), V rows of g_qkv (+2*AD), stride QKV3.
// ---------------------------------------------------------------------------
__global__ __launch_bounds__(256) void pv_kernel(float* __restrict__ y)
{
    __shared__ float Ps[16][128];
    __shared__ float Vs[16][128];
    const int tid = threadIdx.x;
    const int tx = tid & 15, ty = tid >> 4;
    const int b = blockIdx.z;
    const int m0 = blockIdx.y * 128;     // query rows
    const int n0 = blockIdx.x * 128;     // output feature cols
    const float* P = g_sc  + (size_t)b * SS * SS;
    const float* V = g_qkv + (size_t)b * SS * QKV3 + 2*AD;
    const int kend = m0 + 128;           // keys j >= m0+128 are all zero prob

    float acc[8][8] = {};

    for (int k0 = 0; k0 < kend; k0 += 16) {
        #pragma unroll
        for (int q = 0; q < 2; ++q) {
            int f = tid * 2 + q;         // 0..511
            // P tile: rows m (128), k panel 16 — transpose into Ps[k][m]
            int m  = f >> 2;
            int kq = (f & 3) * 4;
            float4 vp = *(const float4*)&P[(size_t)(m0 + m) * SS + k0 + kq];
            Ps[kq+0][m] = vp.x; Ps[kq+1][m] = vp.y; Ps[kq+2][m] = vp.z; Ps[kq+3][m] = vp.w;
            // V tile: 16 k-rows x 128 n-cols, natural layout Vs[k][n]
            int kk = f >> 5;
            int nq = (f & 31) * 4;
            float4 vv = *(const float4*)&V[(size_t)(k0 + kk) * QKV3 + n0 + nq];
            *(float4*)&Vs[kk][nq] = vv;
        }
        __syncthreads();
        #pragma unroll
        for (int k = 0; k < 16; ++k) {
            float4 a0 = *(const float4*)&Ps[k][ty*8];
            float4 a1 = *(const float4*)&Ps[k][ty*8+4];
            float4 b0 = *(const float4*)&Vs[k][tx*8];
            float4 b1 = *(const float4*)&Vs[k][tx*8+4];
            float a[8] = {a0.x,a0.y,a0.z,a0.w,a1.x,a1.y,a1.z,a1.w};
            float bb[8] = {b0.x,b0.y,b0.z,b0.w,b1.x,b1.y,b1.z,b1.w};
            #pragma unroll
            for (int i = 0; i < 8; ++i)
                #pragma unroll
                for (int j = 0; j < 8; ++j)
                    acc[i][j] += a[i] * bb[j];
        }
        __syncthreads();
    }

    #pragma unroll
    for (int i = 0; i < 8; ++i) {
        size_t row = (size_t)b * SS + (m0 + ty*8 + i);
        #pragma unroll
        for (int j = 0; j < 8; ++j)
            y[row * AD + (n0 + tx*8 + j)] = acc[i][j];
    }
}

// ---------------------------------------------------------------------------
extern "C" void kernel_launch(void* const* d_in, const int* in_sizes, int n_in,
                              void* d_out, int out_size)
{
    const float* x    = (const float*)d_in[0];   // [B,S,DIM]
    const float* W    = (const float*)d_in[1];   // [3*AD, DIM]
    const float* bias = (const float*)d_in[2];   // [3*AD]
    float* y = (float*)d_out;                    // [B,S,AD]

    qkv_kernel   <<<dim3(QKV3/128, (BB*SS)/128), 256>>>(x, W, bias);
    scores_kernel<<<dim3(SS/128, SS/128, BB),    256>>>();
    softmax_kernel<<<dim3(SS, BB),               256>>>();
    pv_kernel    <<<dim3(AD/128, SS/128, BB),    256>>>(y);
}

// round 5
// speedup vs baseline: 2.3321x; 2.3321x over previous
#include <cuda_runtime.h>
#include <cuda_bf16.h>
#include <cstdint>
#include <math.h>

#define BB   2
#define SS   4096
#define DIM  1024
#define AD   1024
#define QKV3 (3*AD)

// ---------------------------------------------------------------------------
// Device scratch (no dynamic allocation allowed)
// ---------------------------------------------------------------------------
__device__ __nv_bfloat16 g_xh[(size_t)BB*SS*DIM];    // x hi           [8192,1024]
__device__ __nv_bfloat16 g_xl[(size_t)BB*SS*DIM];    // x lo
__device__ __nv_bfloat16 g_wh[(size_t)QKV3*DIM];     // W hi           [3072,1024]
__device__ __nv_bfloat16 g_wl[(size_t)QKV3*DIM];     // W lo
__device__ __nv_bfloat16 g_qh[(size_t)BB*SS*AD];     // Q hi           [8192,1024]
__device__ __nv_bfloat16 g_ql[(size_t)BB*SS*AD];
__device__ __nv_bfloat16 g_kh[(size_t)BB*SS*AD];     // K hi
__device__ __nv_bfloat16 g_kl[(size_t)BB*SS*AD];
__device__ float         g_v [(size_t)BB*SS*AD];     // V fp32
__device__ __nv_bfloat16 g_vth[(size_t)BB*AD*SS];    // V^T hi         [B,AD,S]
__device__ __nv_bfloat16 g_vtl[(size_t)BB*AD*SS];
__device__ float         g_sc[(size_t)BB*SS*SS];     // raw scores fp32
__device__ __nv_bfloat16 g_ph[(size_t)BB*SS*SS];     // probs hi
__device__ __nv_bfloat16 g_pl[(size_t)BB*SS*SS];     // probs lo

// ---------------------------------------------------------------------------
// PTX helpers (compute_103-safe: cp.async + ldmatrix + mma.sync only)
// ---------------------------------------------------------------------------
static __device__ __forceinline__ uint32_t smem_u32(const void* p) {
    uint32_t a;
    asm("{ .reg .u64 t; cvta.to.shared.u64 t, %1; cvt.u32.u64 %0, t; }" : "=r"(a) : "l"(p));
    return a;
}
#define CP_ASYNC16(dst, src) \
    asm volatile("cp.async.cg.shared.global [%0], [%1], 16;" :: "r"(dst), "l"(src))
#define CP_COMMIT() asm volatile("cp.async.commit_group;" ::: "memory")
#define CP_WAIT(n)  asm volatile("cp.async.wait_group %0;" :: "n"(n) : "memory")

static __device__ __forceinline__ void ldsm4(uint32_t& r0, uint32_t& r1, uint32_t& r2, uint32_t& r3, uint32_t addr) {
    asm volatile("ldmatrix.sync.aligned.m8n8.x4.shared.b16 {%0,%1,%2,%3}, [%4];"
                 : "=r"(r0), "=r"(r1), "=r"(r2), "=r"(r3) : "r"(addr));
}
static __device__ __forceinline__ void mma16816(float* c,
                                                uint32_t a0, uint32_t a1, uint32_t a2, uint32_t a3,
                                                uint32_t b0, uint32_t b1) {
    asm volatile("mma.sync.aligned.m16n8k16.row.col.f32.bf16.bf16.f32 "
                 "{%0,%1,%2,%3}, {%4,%5,%6,%7}, {%8,%9}, {%0,%1,%2,%3};"
                 : "+f"(c[0]), "+f"(c[1]), "+f"(c[2]), "+f"(c[3])
                 : "r"(a0), "r"(a1), "r"(a2), "r"(a3), "r"(b0), "r"(b1));
}

static __device__ __forceinline__ void store_split2(__nv_bfloat16* H, __nv_bfloat16* L,
                                                    size_t idx, float v0, float v1) {
    __nv_bfloat162 h = __floats2bfloat162_rn(v0, v1);
    __nv_bfloat162 l = __floats2bfloat162_rn(v0 - __bfloat162float(h.x),
                                             v1 - __bfloat162float(h.y));
    *(__nv_bfloat162*)(H + idx) = h;
    *(__nv_bfloat162*)(L + idx) = l;
}

// ---------------------------------------------------------------------------
// Shared HMMA core: C[128x128] += A[128xK] * B[128xK]^T, bf16x3 emulation.
// A,B stored K-major bf16 (hi & lo). 256 threads. Double-buffered cp.async.
// smem stage: Ah Al Bh Bl, 128 rows x 80B each (64B data + 16B pad).
// ---------------------------------------------------------------------------
#define T_BYTES    10240           // 128 rows * 80B
#define STAGE_B    (4*T_BYTES)     // 40960
#define SMEM_TOTAL (2*STAGE_B)     // 81920

static __device__ __forceinline__ void stage_tile(uint32_t sdst, const __nv_bfloat16* src,
                                                  int ld, int tid) {
    #pragma unroll
    for (int i = 0; i < 2; ++i) {
        int ci = tid * 2 + i;              // 0..511
        int r = ci >> 2, c = ci & 3;
        CP_ASYNC16(sdst + r * 80 + c * 16, (const char*)(src + (size_t)r * ld) + c * 16);
    }
}

static __device__ __forceinline__ void gemm128(
    const __nv_bfloat16* __restrict__ Ah, const __nv_bfloat16* __restrict__ Al, int lda,
    const __nv_bfloat16* __restrict__ Bh, const __nv_bfloat16* __restrict__ Bl, int ldb,
    int nChunks, char* smem, float acc[16][4])
{
    const int tid  = threadIdx.x;
    const int lane = tid & 31;
    const int w    = tid >> 5;
    const int m_off = (w >> 2) * 64;
    const int n_off = (w & 3) * 32;
    uint32_t sb = smem_u32(smem);

    // ldmatrix lane-address components
    const uint32_t a_row  = (uint32_t)(lane & 15);
    const uint32_t a_koff = (uint32_t)((lane >> 4) & 1) * 16;
    const uint32_t b_row  = (uint32_t)(((lane >> 4) << 3) + (lane & 7));
    const uint32_t b_koff = (uint32_t)((lane >> 3) & 1) * 16;

    // prefetch stage 0
    {
        uint32_t st = sb;
        stage_tile(st,             Ah, lda, tid);
        stage_tile(st + T_BYTES,   Al, lda, tid);
        stage_tile(st + 2*T_BYTES, Bh, ldb, tid);
        stage_tile(st + 3*T_BYTES, Bl, ldb, tid);
        CP_COMMIT();
    }

    for (int i = 0; i < nChunks; ++i) {
        if (i + 1 < nChunks) {
            uint32_t st = sb + ((i + 1) & 1) * STAGE_B;
            stage_tile(st,             Ah + (size_t)(i + 1) * 32, lda, tid);
            stage_tile(st + T_BYTES,   Al + (size_t)(i + 1) * 32, lda, tid);
            stage_tile(st + 2*T_BYTES, Bh + (size_t)(i + 1) * 32, ldb, tid);
            stage_tile(st + 3*T_BYTES, Bl + (size_t)(i + 1) * 32, ldb, tid);
            CP_COMMIT();
            CP_WAIT(1);
        } else {
            CP_WAIT(0);
        }
        __syncthreads();

        uint32_t st = sb + (i & 1) * STAGE_B;
        #pragma unroll
        for (int k16 = 0; k16 < 2; ++k16) {
            uint32_t kb = k16 * 32;       // 16 bf16 = 32 bytes
            uint32_t bh[8], bl[8];
            #pragma unroll
            for (int h = 0; h < 2; ++h) {
                uint32_t addr = st + 2*T_BYTES + (uint32_t)(n_off + h*16 + b_row) * 80 + kb + b_koff;
                ldsm4(bh[h*4], bh[h*4+1], bh[h*4+2], bh[h*4+3], addr);
                ldsm4(bl[h*4], bl[h*4+1], bl[h*4+2], bl[h*4+3], addr + T_BYTES);
            }
            #pragma unroll
            for (int mf = 0; mf < 4; ++mf) {
                uint32_t addr = st + (uint32_t)(m_off + mf*16 + a_row) * 80 + kb + a_koff;
                uint32_t h0, h1, h2, h3, l0, l1, l2, l3;
                ldsm4(h0, h1, h2, h3, addr);
                ldsm4(l0, l1, l2, l3, addr + T_BYTES);
                #pragma unroll
                for (int nf = 0; nf < 4; ++nf) {
                    float* c = acc[mf*4 + nf];
                    uint32_t B0 = bh[nf*2], B1 = bh[nf*2+1];
                    mma16816(c, h0, h1, h2, h3, B0, B1);               // Ah*Bh
                    mma16816(c, h0, h1, h2, h3, bl[nf*2], bl[nf*2+1]); // Ah*Bl
                    mma16816(c, l0, l1, l2, l3, B0, B1);               // Al*Bh
                }
            }
        }
        __syncthreads();
    }
}

// ---------------------------------------------------------------------------
// Split kernels: fp32 -> bf16 hi/lo. Device globals referenced IN DEVICE CODE
// (host code must never take a __device__ symbol's address).
// ---------------------------------------------------------------------------
__global__ void __launch_bounds__(256) split_x_kernel(const float* __restrict__ s) {
    int i = (blockIdx.x * 256 + threadIdx.x) * 4;
    float4 v = *(const float4*)(s + i);
    store_split2(g_xh, g_xl, i,     v.x, v.y);
    store_split2(g_xh, g_xl, i + 2, v.z, v.w);
}
__global__ void __launch_bounds__(256) split_w_kernel(const float* __restrict__ s) {
    int i = (blockIdx.x * 256 + threadIdx.x) * 4;
    float4 v = *(const float4*)(s + i);
    store_split2(g_wh, g_wl, i,     v.x, v.y);
    store_split2(g_wh, g_wl, i + 2, v.z, v.w);
}

// ---------------------------------------------------------------------------
// QKV GEMM: [8192,3072] = x @ W^T + bias; route N-segments to Q/K split, V fp32
// ---------------------------------------------------------------------------
__global__ void __launch_bounds__(256, 1) qkv_mma(const float* __restrict__ bias) {
    extern __shared__ __align__(128) char sm[];
    const int m0 = blockIdx.y * 128, n0 = blockIdx.x * 128;
    const int lane = threadIdx.x & 31, w = threadIdx.x >> 5;
    const int m_off = (w >> 2) * 64, n_off = (w & 3) * 32;

    float acc[16][4];
    #pragma unroll
    for (int i = 0; i < 16; ++i)
        #pragma unroll
        for (int j = 0; j < 4; ++j) acc[i][j] = 0.0f;

    gemm128(g_xh + (size_t)m0 * DIM, g_xl + (size_t)m0 * DIM, DIM,
            g_wh + (size_t)n0 * DIM, g_wl + (size_t)n0 * DIM, DIM,
            DIM / 32, sm, acc);

    #pragma unroll
    for (int mf = 0; mf < 4; ++mf) {
        #pragma unroll
        for (int nf = 0; nf < 4; ++nf) {
            float* c = acc[mf*4 + nf];
            int r  = m0 + m_off + mf*16 + (lane >> 2);
            int cg = n0 + n_off + nf*8 + ((lane & 3) << 1);
            float b0 = bias[cg], b1 = bias[cg + 1];
            float v0 = c[0] + b0, v1 = c[1] + b1;     // row r
            float v2 = c[2] + b0, v3 = c[3] + b1;     // row r+8
            if (cg < AD) {
                store_split2(g_qh, g_ql, (size_t)r * AD + cg,       v0, v1);
                store_split2(g_qh, g_ql, (size_t)(r + 8) * AD + cg, v2, v3);
            } else if (cg < 2*AD) {
                int ck = cg - AD;
                store_split2(g_kh, g_kl, (size_t)r * AD + ck,       v0, v1);
                store_split2(g_kh, g_kl, (size_t)(r + 8) * AD + ck, v2, v3);
            } else {
                int cv = cg - 2*AD;
                *(float2*)(g_v + (size_t)r * AD + cv)       = make_float2(v0, v1);
                *(float2*)(g_v + (size_t)(r + 8) * AD + cv) = make_float2(v2, v3);
            }
        }
    }
}

// ---------------------------------------------------------------------------
// V transpose + split: g_v [B,S,AD] -> g_vth/g_vtl [B,AD,S]
// ---------------------------------------------------------------------------
__global__ void __launch_bounds__(256) vt_split_kernel() {
    __shared__ float t[32][33];
    const int b = blockIdx.z;
    const int k0 = blockIdx.x * 32, n0 = blockIdx.y * 32;
    const int tx = threadIdx.x, ty = threadIdx.y;     // 32 x 8
    const float* V = g_v + (size_t)b * SS * AD;
    #pragma unroll
    for (int j = 0; j < 4; ++j)
        t[ty + j * 8][tx] = V[(size_t)(k0 + ty + j * 8) * AD + n0 + tx];
    __syncthreads();
    #pragma unroll
    for (int j = 0; j < 4; ++j) {
        int n = n0 + ty + j * 8;
        int k = k0 + tx;
        float v = t[tx][ty + j * 8];
        __nv_bfloat16 h = __float2bfloat16(v);
        __nv_bfloat16 l = __float2bfloat16(v - __bfloat162float(h));
        size_t idx = ((size_t)b * AD + n) * SS + k;
        g_vth[idx] = h;
        g_vtl[idx] = l;
    }
}

// ---------------------------------------------------------------------------
// Scores GEMM: S = Q @ K^T, lower-triangular 128x128 blocks only, fp32 out
// ---------------------------------------------------------------------------
__global__ void __launch_bounds__(256, 1) scores_mma() {
    const int bx = blockIdx.x, by = blockIdx.y, b = blockIdx.z;
    if (bx > by) return;
    extern __shared__ __align__(128) char sm[];
    const int m0 = by * 128, n0 = bx * 128;
    const int lane = threadIdx.x & 31, w = threadIdx.x >> 5;
    const int m_off = (w >> 2) * 64, n_off = (w & 3) * 32;

    float acc[16][4];
    #pragma unroll
    for (int i = 0; i < 16; ++i)
        #pragma unroll
        for (int j = 0; j < 4; ++j) acc[i][j] = 0.0f;

    const size_t qo = ((size_t)b * SS + m0) * AD;
    const size_t ko = ((size_t)b * SS + n0) * AD;
    gemm128(g_qh + qo, g_ql + qo, AD, g_kh + ko, g_kl + ko, AD, AD / 32, sm, acc);

    float* dst = g_sc + (size_t)b * SS * SS;
    #pragma unroll
    for (int mf = 0; mf < 4; ++mf) {
        #pragma unroll
        for (int nf = 0; nf < 4; ++nf) {
            float* c = acc[mf*4 + nf];
            int r  = m0 + m_off + mf*16 + (lane >> 2);
            int cg = n0 + n_off + nf*8 + ((lane & 3) << 1);
            *(float2*)(dst + (size_t)r * SS + cg)       = make_float2(c[0], c[1]);
            *(float2*)(dst + (size_t)(r + 8) * SS + cg) = make_float2(c[2], c[3]);
        }
    }
}

// ---------------------------------------------------------------------------
// Causal softmax (scale 1/32): fp32 scores -> bf16 hi/lo probs, zero tail
// ---------------------------------------------------------------------------
__global__ void __launch_bounds__(256) softmax_kernel() {
    const int i = blockIdx.x, b = blockIdx.y, tid = threadIdx.x;
    const float* row = g_sc + (size_t)b * SS * SS + (size_t)i * SS;
    __nv_bfloat16* ph = g_ph + (size_t)b * SS * SS + (size_t)i * SS;
    __nv_bfloat16* pl = g_pl + (size_t)b * SS * SS + (size_t)i * SS;
    const int len = i + 1;
    const float inv = 1.0f / 32.0f;
    __shared__ float red[256];

    float m = -3.4e38f;
    for (int j = tid; j < len; j += 256) m = fmaxf(m, row[j]);
    red[tid] = m; __syncthreads();
    for (int s = 128; s > 0; s >>= 1) { if (tid < s) red[tid] = fmaxf(red[tid], red[tid + s]); __syncthreads(); }
    m = red[0]; __syncthreads();

    float sum = 0.0f;
    for (int j = tid; j < len; j += 256) sum += expf((row[j] - m) * inv);
    red[tid] = sum; __syncthreads();
    for (int s = 128; s > 0; s >>= 1) { if (tid < s) red[tid] += red[tid + s]; __syncthreads(); }
    const float rs = 1.0f / red[0];

    for (int j = tid; j < len; j += 256) {
        float p = expf((row[j] - m) * inv) * rs;
        __nv_bfloat16 h = __float2bfloat16(p);
        ph[j] = h;
        pl[j] = __float2bfloat16(p - __bfloat162float(h));
    }
    const __nv_bfloat16 z = __float2bfloat16(0.0f);
    for (int j = len + tid; j < SS; j += 256) { ph[j] = z; pl[j] = z; }
}

// ---------------------------------------------------------------------------
// PV GEMM: y = P @ V (K truncated at causal boundary), fp32 out
// ---------------------------------------------------------------------------
__global__ void __launch_bounds__(256, 1) pv_mma(float* __restrict__ y) {
    extern __shared__ __align__(128) char sm[];
    const int b = blockIdx.z;
    const int m0 = blockIdx.y * 128, n0 = blockIdx.x * 128;
    const int lane = threadIdx.x & 31, w = threadIdx.x >> 5;
    const int m_off = (w >> 2) * 64, n_off = (w & 3) * 32;

    float acc[16][4];
    #pragma unroll
    for (int i = 0; i < 16; ++i)
        #pragma unroll
        for (int j = 0; j < 4; ++j) acc[i][j] = 0.0f;

    const size_t po = ((size_t)b * SS + m0) * SS;
    const size_t vo = ((size_t)b * AD + n0) * SS;
    gemm128(g_ph + po, g_pl + po, SS, g_vth + vo, g_vtl + vo, SS,
            (blockIdx.y + 1) * 4, sm, acc);

    #pragma unroll
    for (int mf = 0; mf < 4; ++mf) {
        #pragma unroll
        for (int nf = 0; nf < 4; ++nf) {
            float* c = acc[mf*4 + nf];
            int r  = m0 + m_off + mf*16 + (lane >> 2);
            int cg = n0 + n_off + nf*8 + ((lane & 3) << 1);
            *(float2*)(y + ((size_t)b * SS + r) * AD + cg)       = make_float2(c[0], c[1]);
            *(float2*)(y + ((size_t)b * SS + r + 8) * AD + cg)   = make_float2(c[2], c[3]);
        }
    }
}

// ---------------------------------------------------------------------------
extern "C" void kernel_launch(void* const* d_in, const int* in_sizes, int n_in,
                              void* d_out, int out_size)
{
    const float* x    = (const float*)d_in[0];   // [B,S,DIM]
    const float* W    = (const float*)d_in[1];   // [3*AD, DIM]
    const float* bias = (const float*)d_in[2];   // [3*AD]
    float* y = (float*)d_out;                    // [B,S,AD]

    cudaFuncSetAttribute(qkv_mma,    cudaFuncAttributeMaxDynamicSharedMemorySize, SMEM_TOTAL);
    cudaFuncSetAttribute(scores_mma, cudaFuncAttributeMaxDynamicSharedMemorySize, SMEM_TOTAL);
    cudaFuncSetAttribute(pv_mma,     cudaFuncAttributeMaxDynamicSharedMemorySize, SMEM_TOTAL);

    split_x_kernel<<<(BB*SS*DIM) / 1024, 256>>>(x);
    split_w_kernel<<<(QKV3*DIM) / 1024, 256>>>(W);
    qkv_mma   <<<dim3(QKV3/128, (BB*SS)/128), 256, SMEM_TOTAL>>>(bias);
    vt_split_kernel<<<dim3(SS/32, AD/32, BB), dim3(32, 8)>>>();
    scores_mma<<<dim3(SS/128, SS/128, BB), 256, SMEM_TOTAL>>>();
    softmax_kernel<<<dim3(SS, BB), 256>>>();
    pv_mma    <<<dim3(AD/128, SS/128, BB), 256, SMEM_TOTAL>>>(y);
}